// round 6
// baseline (speedup 1.0000x reference)
#include <cuda_runtime.h>
#include <cstdint>
#include <cstddef>
#include <climits>

#define NNODE 1500
#define T_IN  168
#define TLEN  162
#define BATCH 8
#define CH    16
#define EMBD  16
#define KTOP  12
#define NBRS  13            // KTOP + self
#define FDIM  (BATCH*CH*TLEN)   // 20736
#define ALPHA 1.5f
#define BETA  0.2f

#define PCH   16            // f-chunk per prop block
#define PPAD  17            // padded row stride in prop smem

// ---------------- device scratch (no allocations allowed) ----------------
__device__ float g_H0[(size_t)NNODE * FDIM];
__device__ float g_H1[(size_t)NNODE * FDIM];
__device__ float g_H2[(size_t)NNODE * FDIM];
__device__ float g_m1[NNODE * EMBD];
__device__ float g_m2[NNODE * EMBD];
__device__ float g_weff[CH * 8];
__device__ float g_beff[CH];
__device__ int   g_nbr[NNODE * NBRS];
__device__ float g_nw [NNODE * NBRS];

// ---------------- packed fp32x2 FMA (sm_103a FFMA2) ----------------
__device__ __forceinline__ float2 ffma2(float2 a, float2 b, float2 c) {
    unsigned long long au = *reinterpret_cast<unsigned long long*>(&a);
    unsigned long long bu = *reinterpret_cast<unsigned long long*>(&b);
    unsigned long long cu = *reinterpret_cast<unsigned long long*>(&c);
    unsigned long long du;
    asm("fma.rn.f32x2 %0, %1, %2, %3;" : "=l"(du) : "l"(au), "l"(bu), "l"(cu));
    return *reinterpret_cast<float2*>(&du);
}

// ============ K0: combined prep (weff fold + embedding transform) ============
__global__ void k_prep(const float* pw, const float* pb,
                       const float* tw2, const float* tb2,
                       const float* tw3, const float* tb3,
                       const float* tw6, const float* tb6,
                       const float* tw7, const float* tb7,
                       const float* e1, const float* gw1, const float* gb1,
                       const float* e2, const float* gw2, const float* gb2) {
    int n = blockIdx.x * 128 + threadIdx.x;
    if (n < NNODE) {
        float ev1[EMBD], ev2[EMBD];
#pragma unroll
        for (int i = 0; i < EMBD; i++) { ev1[i] = e1[n * EMBD + i]; ev2[i] = e2[n * EMBD + i]; }
#pragma unroll
        for (int e = 0; e < EMBD; e++) {
            float a1 = gb1[e], a2 = gb2[e];
#pragma unroll
            for (int k = 0; k < EMBD; k++) {
                a1 += ev1[k] * gw1[k * EMBD + e];
                a2 += ev2[k] * gw2[k * EMBD + e];
            }
            g_m1[n * EMBD + e] = tanhf(ALPHA * a1);
            g_m2[n * EMBD + e] = tanhf(ALPHA * a2);
        }
    }
    if (blockIdx.x == 0 && threadIdx.x < CH) {
        int c = threadIdx.x;
        int br = c >> 2, o = c & 3;
        const float* tw; const float* tb; int k;
        if      (br == 0) { tw = tw2; tb = tb2; k = 2; }
        else if (br == 1) { tw = tw3; tb = tb3; k = 3; }
        else if (br == 2) { tw = tw6; tb = tb6; k = 6; }
        else              { tw = tw7; tb = tb7; k = 7; }
        float bacc = tb[o];
        for (int j = 0; j < k; j++) {
            float wacc = 0.f;
            for (int ci = 0; ci < CH; ci++) {
                float w = tw[(o * CH + ci) * k + j];
                wacc += w * pw[ci];
                bacc += w * pb[ci];
            }
            g_weff[c * 8 + j] = wacc;
        }
        g_beff[c] = bacc;
    }
}

// ============ K1: warp-level tournament top-12 (no barriers in hot loop) ============
#define SEG 188                       // ceil(1500 / 8)
#define SLOTS 6                       // ceil(SEG / 32)

__global__ void k_topk() {
    int v = blockIdx.x;
    int tid = threadIdx.x;            // 256 threads, 8 warps
    int w = tid >> 5, lane = tid & 31;

    float m1v[EMBD], m2v[EMBD];
#pragma unroll
    for (int e = 0; e < EMBD; e++) { m1v[e] = g_m1[v * EMBD + e]; m2v[e] = g_m2[v * EMBD + e]; }

    int base = w * SEG;
    int segEnd = min(base + SEG, NNODE);
    float vals[SLOTS];
    int   idxs[SLOTS];
#pragma unroll
    for (int k = 0; k < SLOTS; k++) {
        int idx = base + k * 32 + lane;
        if (idx < segEnd) {
            const float4* p2 = (const float4*)(g_m2 + idx * EMBD);
            const float4* p1 = (const float4*)(g_m1 + idx * EMBD);
            float d = 0.f;
#pragma unroll
            for (int q = 0; q < 4; q++) {
                float4 a2 = p2[q], a1 = p1[q];
                d += m1v[4*q+0]*a2.x - m2v[4*q+0]*a1.x;
                d += m1v[4*q+1]*a2.y - m2v[4*q+1]*a1.y;
                d += m1v[4*q+2]*a2.z - m2v[4*q+2]*a1.z;
                d += m1v[4*q+3]*a2.w - m2v[4*q+3]*a1.w;
            }
            float a = tanhf(ALPHA * d);
            vals[k] = a > 0.f ? a : 0.f;
            idxs[k] = idx;
        } else {
            vals[k] = -1.f;
            idxs[k] = INT_MAX;
        }
    }

    __shared__ float swv[8][KTOP];
    __shared__ int   swi[8][KTOP];

#pragma unroll
    for (int it = 0; it < KTOP; it++) {
        float bv = -1.f; int bi = INT_MAX;
#pragma unroll
        for (int k = 0; k < SLOTS; k++)
            if (vals[k] > bv || (vals[k] == bv && idxs[k] < bi)) { bv = vals[k]; bi = idxs[k]; }
#pragma unroll
        for (int off = 16; off; off >>= 1) {
            float ov = __shfl_xor_sync(0xffffffffu, bv, off);
            int   oi = __shfl_xor_sync(0xffffffffu, bi, off);
            if (ov > bv || (ov == bv && oi < bi)) { bv = ov; bi = oi; }
        }
#pragma unroll
        for (int k = 0; k < SLOTS; k++)
            if (idxs[k] == bi) vals[k] = -1.f;
        if (lane == 0) { swv[w][it] = bv; swi[w][it] = bi; }
    }
    __syncthreads();

    if (w == 0) {
        float mv[3]; int mi[3];
#pragma unroll
        for (int k = 0; k < 3; k++) {
            int j = lane + 32 * k;
            if (j < 96) { mv[k] = swv[j / KTOP][j % KTOP]; mi[k] = swi[j / KTOP][j % KTOP]; }
            else        { mv[k] = -1.f; mi[k] = INT_MAX; }
        }
        float myv = -1.f; int myi = 0;
        float sum = 0.f;
#pragma unroll
        for (int it = 0; it < KTOP; it++) {
            float bv = -1.f; int bi = INT_MAX;
#pragma unroll
            for (int k = 0; k < 3; k++)
                if (mv[k] > bv || (mv[k] == bv && mi[k] < bi)) { bv = mv[k]; bi = mi[k]; }
#pragma unroll
            for (int off = 16; off; off >>= 1) {
                float ov = __shfl_xor_sync(0xffffffffu, bv, off);
                int   oi = __shfl_xor_sync(0xffffffffu, bi, off);
                if (ov > bv || (ov == bv && oi < bi)) { bv = ov; bi = oi; }
            }
#pragma unroll
            for (int k = 0; k < 3; k++)
                if (mi[k] == bi) mv[k] = -1.f;
            if (lane == it) { myv = bv; myi = bi; }
            sum += bv;
        }
        float inv = 1.f / (1.f + sum);
        if (lane < KTOP) {
            g_nbr[v * NBRS + lane] = myi;
            g_nw [v * NBRS + lane] = myv * inv;
        }
        if (lane == 0) {
            g_nbr[v * NBRS + KTOP] = v;
            g_nw [v * NBRS + KTOP] = inv;
        }
    }
}

// ============ K2: folded inception temporal conv -> H0[N][b][c][t] ============
__device__ __forceinline__ constexpr int KC(int c) {
    return c < 4 ? 2 : (c < 8 ? 3 : (c < 12 ? 6 : 7));
}

__global__ void k_tconv(const float* __restrict__ x) {
    int n = blockIdx.x;
    int tid = threadIdx.x;                    // 192 threads
    __shared__ float xs[BATCH][T_IN];
    __shared__ float swv[128];
    __shared__ float sbv[16];
    for (int i = tid; i < BATCH * T_IN; i += 192) {
        int b = i / T_IN, t = i - b * T_IN;
        xs[b][t] = x[(size_t)(b * T_IN + t) * NNODE + n];
    }
    if (tid < 128) swv[tid] = g_weff[tid];
    if (tid < 16)  sbv[tid] = g_beff[tid];
    __syncthreads();
    if (tid >= TLEN) return;

    float wr[16][8];
#pragma unroll
    for (int c = 0; c < 16; c++) {
        const int k = KC(c);
#pragma unroll
        for (int j = 0; j < 8; j++)
            if (j < k) wr[c][j] = swv[c * 8 + j];
    }
    float bb[16];
#pragma unroll
    for (int c = 0; c < 16; c++) bb[c] = sbv[c];

    float* outp = g_H0 + (size_t)n * FDIM + tid;
#pragma unroll
    for (int b = 0; b < BATCH; b++) {
#pragma unroll
        for (int c = 0; c < 16; c++) {
            const int k = KC(c);
            float acc = bb[c];
#pragma unroll
            for (int j = 0; j < k; j++)
                acc = fmaf(wr[c][j], xs[b][tid + 7 - k + j], acc);
            outp[(size_t)(b * 16 + c) * TLEN] = fmaxf(acc, 0.f);
        }
    }
}

// ============ K3: fused two-hop mixprop, smem-staged per f-chunk ============
// S0 = H0 chunk for all nodes; hop1: H1 = b*S0 + (1-b)*A*S0 (also kept in S1);
// hop2: H2 = b*S0 + (1-b)*A*S1.
__global__ __launch_bounds__(1024, 1) void k_prop2() {
    extern __shared__ float S[];
    float* S0 = S;                        // [NNODE][PPAD]
    float* S1 = S + NNODE * PPAD;
    int base = blockIdx.x * PCH;
    int tid = threadIdx.x;                // 1024 threads, 32 warps

    for (int idx = tid; idx < NNODE * PCH; idx += 1024) {
        int nn = idx >> 4, i = idx & 15;
        S0[nn * PPAD + i] = g_H0[(size_t)nn * FDIM + base + i];
    }
    __syncthreads();

    int lane = tid & 31, w = tid >> 5;
    int half = lane >> 4, i = lane & 15;

    // hop 1
    for (int v = w * 2 + half; v < NNODE; v += 64) {
        const int*   nbp = g_nbr + v * NBRS;
        const float* nwp = g_nw  + v * NBRS;
        float acc = 0.f;
#pragma unroll
        for (int j = 0; j < NBRS; j++)
            acc += nwp[j] * S0[nbp[j] * PPAD + i];
        float h1 = BETA * S0[v * PPAD + i] + (1.f - BETA) * acc;
        S1[v * PPAD + i] = h1;
        g_H1[(size_t)v * FDIM + base + i] = h1;
    }
    __syncthreads();

    // hop 2
    for (int v = w * 2 + half; v < NNODE; v += 64) {
        const int*   nbp = g_nbr + v * NBRS;
        const float* nwp = g_nw  + v * NBRS;
        float acc = 0.f;
#pragma unroll
        for (int j = 0; j < NBRS; j++)
            acc += nwp[j] * S1[nbp[j] * PPAD + i];
        float h2 = BETA * S0[v * PPAD + i] + (1.f - BETA) * acc;
        g_H2[(size_t)v * FDIM + base + i] = h2;
    }
}

// ============ K5: MLP head, weights in SMEM, f32x2, 6 t's per thread ============
__global__ __launch_bounds__(224, 2) void k_final(
    const float* __restrict__ mw,  const float* __restrict__ mb,
    const float* __restrict__ rw1, const float* __restrict__ rb1,
    const float* __restrict__ rw2, const float* __restrict__ rb2,
    float* __restrict__ out) {
    int v = blockIdx.x;
    int tid = threadIdx.x;                 // 224 threads; 216 active in main phase
    __shared__ float2 sg[768];             // mw dup pairs: [j][hop*16+c]
    __shared__ float2 sr1[256];            // rw1 dup pairs
    __shared__ float  s_mb[16], s_rb1[16], s_rw2[384], s_rb2[24];
    __shared__ float  part[216][16];
    __shared__ float  rm[8][16];

    for (int idx = tid; idx < 768; idx += 224) { float w = mw[idx];  sg[idx]  = make_float2(w, w); }
    for (int idx = tid; idx < 256; idx += 224) { float w = rw1[idx]; sr1[idx] = make_float2(w, w); }
    for (int idx = tid; idx < 384; idx += 224) s_rw2[idx] = rw2[idx];
    if (tid < 16) { s_mb[tid] = mb[tid]; s_rb1[tid] = rb1[tid]; }
    if (tid < 24) s_rb2[tid] = rb2[tid];
    __syncthreads();

    if (tid < 216) {
        int b = tid / 27;
        int i = tid - b * 27;
        int t0 = i * 6;                    // 27*6 = 162 exactly
        size_t off = (size_t)v * FDIM + (size_t)b * (CH * TLEN) + t0;

        float2 z0[16], z1[16], z2[16];
#pragma unroll
        for (int j = 0; j < 16; j++) {
            float m = s_mb[j];
            z0[j] = make_float2(m, m); z1[j] = z0[j]; z2[j] = z0[j];
        }

#pragma unroll
        for (int s = 0; s < 3; s++) {
            const float* bp = (s == 0 ? g_H0 : (s == 1 ? g_H1 : g_H2)) + off;
#pragma unroll
            for (int c = 0; c < 16; c++) {
                const float* p = bp + (size_t)c * TLEN;
                float2 h0 = *reinterpret_cast<const float2*>(p);
                float2 h1 = *reinterpret_cast<const float2*>(p + 2);
                float2 h2 = *reinterpret_cast<const float2*>(p + 4);
#pragma unroll
                for (int j = 0; j < 16; j++) {
                    float2 w = sg[j * 48 + s * 16 + c];
                    z0[j] = ffma2(w, h0, z0[j]);
                    z1[j] = ffma2(w, h1, z1[j]);
                    z2[j] = ffma2(w, h2, z2[j]);
                }
            }
        }

#pragma unroll
        for (int j = 0; j < 16; j++) {
            z0[j].x = fmaxf(z0[j].x, 0.f); z0[j].y = fmaxf(z0[j].y, 0.f);
            z1[j].x = fmaxf(z1[j].x, 0.f); z1[j].y = fmaxf(z1[j].y, 0.f);
            z2[j].x = fmaxf(z2[j].x, 0.f); z2[j].y = fmaxf(z2[j].y, 0.f);
        }

#pragma unroll
        for (int i2 = 0; i2 < 16; i2++) {
            float rb = s_rb1[i2];
            float2 a0 = make_float2(rb, rb), a1 = a0, a2 = a0;
#pragma unroll
            for (int j = 0; j < 16; j++) {
                float2 w = sr1[i2 * 16 + j];
                a0 = ffma2(w, z0[j], a0);
                a1 = ffma2(w, z1[j], a1);
                a2 = ffma2(w, z2[j], a2);
            }
            part[tid][i2] = fmaxf(a0.x, 0.f) + fmaxf(a0.y, 0.f)
                          + fmaxf(a1.x, 0.f) + fmaxf(a1.y, 0.f)
                          + fmaxf(a2.x, 0.f) + fmaxf(a2.y, 0.f);
        }
    }
    __syncthreads();

    if (tid < 128) {
        int b = tid >> 4, i = tid & 15;
        float s = 0.f;
#pragma unroll
        for (int k = 0; k < 27; k++) s += part[b * 27 + k][i];
        rm[b][i] = s * (1.f / (float)TLEN);
    }
    __syncthreads();

    if (tid < 192) {
        int b = tid / 24, o = tid - b * 24;
        float a = s_rb2[o];
#pragma unroll
        for (int c = 0; c < 16; c++) a += s_rw2[o * 16 + c] * rm[b][c];
        out[((size_t)b * 24 + o) * NNODE + v] = a;
    }
}

// ======================= launcher =======================
extern "C" void kernel_launch(void* const* d_in, const int* in_sizes, int n_in,
                              void* d_out, int out_size) {
    const float* x   = (const float*)d_in[0];
    const float* pw  = (const float*)d_in[1];
    const float* pb  = (const float*)d_in[2];
    const float* tw2 = (const float*)d_in[3];
    const float* tb2 = (const float*)d_in[4];
    const float* tw3 = (const float*)d_in[5];
    const float* tb3 = (const float*)d_in[6];
    const float* tw6 = (const float*)d_in[7];
    const float* tb6 = (const float*)d_in[8];
    const float* tw7 = (const float*)d_in[9];
    const float* tb7 = (const float*)d_in[10];
    const float* e1  = (const float*)d_in[11];
    const float* e2  = (const float*)d_in[12];
    const float* gw1 = (const float*)d_in[13];
    const float* gb1 = (const float*)d_in[14];
    const float* gw2 = (const float*)d_in[15];
    const float* gb2 = (const float*)d_in[16];
    const float* mw  = (const float*)d_in[17];
    const float* mb  = (const float*)d_in[18];
    const float* rw1 = (const float*)d_in[19];
    const float* rb1 = (const float*)d_in[20];
    const float* rw2 = (const float*)d_in[21];
    const float* rb2 = (const float*)d_in[22];

    static bool attr_set = false;
    if (!attr_set) {
        cudaFuncSetAttribute(k_prop2, cudaFuncAttributeMaxDynamicSharedMemorySize,
                             2 * NNODE * PPAD * (int)sizeof(float));
        attr_set = true;
    }

    k_prep<<<(NNODE + 127) / 128, 128>>>(pw, pb, tw2, tb2, tw3, tb3, tw6, tb6, tw7, tb7,
                                         e1, gw1, gb1, e2, gw2, gb2);
    k_topk<<<NNODE, 256>>>();
    k_tconv<<<NNODE, 192>>>(x);

    int smem = 2 * NNODE * PPAD * (int)sizeof(float);   // 204 KB
    k_prop2<<<FDIM / PCH, 1024, smem>>>();              // 1296 blocks  (4th launch -> profiled)

    k_final<<<NNODE, 224>>>(mw, mb, rw1, rb1, rw2, rb2, (float*)d_out);
}

// round 8
// speedup vs baseline: 1.5520x; 1.5520x over previous
#include <cuda_runtime.h>
#include <cstdint>
#include <cstddef>
#include <climits>

#define NNODE 1500
#define T_IN  168
#define TLEN  162
#define BATCH 8
#define CH    16
#define EMBD  16
#define KTOP  12
#define NBRS  13            // KTOP + self
#define FDIM  (BATCH*CH*TLEN)   // 20736
#define FDIM4 (FDIM/4)          // 5184
#define ALPHA 1.5f
#define BETA  0.2f

// ---------------- device scratch (no allocations allowed) ----------------
__device__ float g_H0[(size_t)NNODE * FDIM];
__device__ float g_P1[(size_t)NNODE * FDIM];
__device__ float g_P2[(size_t)NNODE * FDIM];
__device__ float g_m1[NNODE * EMBD];
__device__ float g_m2[NNODE * EMBD];
__device__ float g_weff[CH * 8];
__device__ float g_beff[CH];
__device__ int   g_nbr[NNODE * NBRS];
__device__ float g_nw [NNODE * NBRS];
__device__ float g_G[768];          // folded 48->16 weights [j][s*16+c]

// ---------------- packed fp32x2 FMA (sm_103a FFMA2) ----------------
__device__ __forceinline__ float2 ffma2(float2 a, float2 b, float2 c) {
    unsigned long long au = *reinterpret_cast<unsigned long long*>(&a);
    unsigned long long bu = *reinterpret_cast<unsigned long long*>(&b);
    unsigned long long cu = *reinterpret_cast<unsigned long long*>(&c);
    unsigned long long du;
    asm("fma.rn.f32x2 %0, %1, %2, %3;" : "=l"(du) : "l"(au), "l"(bu), "l"(cu));
    return *reinterpret_cast<float2*>(&du);
}

// ============ K0: combined prep (weff fold + embeddings + G fold) ============
__global__ void k_prep(const float* pw, const float* pb,
                       const float* tw2, const float* tb2,
                       const float* tw3, const float* tb3,
                       const float* tw6, const float* tb6,
                       const float* tw7, const float* tb7,
                       const float* e1, const float* gw1, const float* gb1,
                       const float* e2, const float* gw2, const float* gb2,
                       const float* mw) {
    int n = blockIdx.x * 128 + threadIdx.x;
    if (n < NNODE) {
        float ev1[EMBD], ev2[EMBD];
#pragma unroll
        for (int i = 0; i < EMBD; i++) { ev1[i] = e1[n * EMBD + i]; ev2[i] = e2[n * EMBD + i]; }
#pragma unroll
        for (int e = 0; e < EMBD; e++) {
            float a1 = gb1[e], a2 = gb2[e];
#pragma unroll
            for (int k = 0; k < EMBD; k++) {
                a1 += ev1[k] * gw1[k * EMBD + e];
                a2 += ev2[k] * gw2[k * EMBD + e];
            }
            g_m1[n * EMBD + e] = tanhf(ALPHA * a1);
            g_m2[n * EMBD + e] = tanhf(ALPHA * a2);
        }
    }
    if (blockIdx.x == 0) {
        if (threadIdx.x < CH) {
            int c = threadIdx.x;
            int br = c >> 2, o = c & 3;
            const float* tw; const float* tb; int k;
            if      (br == 0) { tw = tw2; tb = tb2; k = 2; }
            else if (br == 1) { tw = tw3; tb = tb3; k = 3; }
            else if (br == 2) { tw = tw6; tb = tb6; k = 6; }
            else              { tw = tw7; tb = tb7; k = 7; }
            float bacc = tb[o];
            for (int j = 0; j < k; j++) {
                float wacc = 0.f;
                for (int ci = 0; ci < CH; ci++) {
                    float w = tw[(o * CH + ci) * k + j];
                    wacc += w * pw[ci];
                    bacc += w * pb[ci];
                }
                g_weff[c * 8 + j] = wacc;
            }
            g_beff[c] = bacc;
        }
        // folded 48->16 layer: z = G0*H0 + G1*P1 + G2*P2
        for (int idx = threadIdx.x; idx < 768; idx += 128) {
            int j = idx / 48, c = idx % 48;
            int hop = c >> 4, ci = c & 15;
            const float* row = mw + j * 48;
            float m1v = row[16 + ci], m2v = row[32 + ci];
            float g;
            if      (hop == 0) g = row[ci] + BETA * m1v + BETA * m2v;
            else if (hop == 1) g = (1.f - BETA) * m1v + BETA * (1.f - BETA) * m2v;
            else               g = (1.f - BETA) * (1.f - BETA) * m2v;
            g_G[idx] = g;
        }
    }
}

// ============ K1: warp-level tournament top-12 (no barriers in hot loop) ============
#define SEG 188                       // ceil(1500 / 8)
#define SLOTS 6                       // ceil(SEG / 32)

__global__ void k_topk() {
    int v = blockIdx.x;
    int tid = threadIdx.x;            // 256 threads, 8 warps
    int w = tid >> 5, lane = tid & 31;

    float m1v[EMBD], m2v[EMBD];
#pragma unroll
    for (int e = 0; e < EMBD; e++) { m1v[e] = g_m1[v * EMBD + e]; m2v[e] = g_m2[v * EMBD + e]; }

    int base = w * SEG;
    int segEnd = min(base + SEG, NNODE);
    float vals[SLOTS];
    int   idxs[SLOTS];
#pragma unroll
    for (int k = 0; k < SLOTS; k++) {
        int idx = base + k * 32 + lane;
        if (idx < segEnd) {
            const float4* p2 = (const float4*)(g_m2 + idx * EMBD);
            const float4* p1 = (const float4*)(g_m1 + idx * EMBD);
            float d = 0.f;
#pragma unroll
            for (int q = 0; q < 4; q++) {
                float4 a2 = p2[q], a1 = p1[q];
                d += m1v[4*q+0]*a2.x - m2v[4*q+0]*a1.x;
                d += m1v[4*q+1]*a2.y - m2v[4*q+1]*a1.y;
                d += m1v[4*q+2]*a2.z - m2v[4*q+2]*a1.z;
                d += m1v[4*q+3]*a2.w - m2v[4*q+3]*a1.w;
            }
            float a = tanhf(ALPHA * d);
            vals[k] = a > 0.f ? a : 0.f;
            idxs[k] = idx;
        } else {
            vals[k] = -1.f;
            idxs[k] = INT_MAX;
        }
    }

    __shared__ float swv[8][KTOP];
    __shared__ int   swi[8][KTOP];

#pragma unroll
    for (int it = 0; it < KTOP; it++) {
        float bv = -1.f; int bi = INT_MAX;
#pragma unroll
        for (int k = 0; k < SLOTS; k++)
            if (vals[k] > bv || (vals[k] == bv && idxs[k] < bi)) { bv = vals[k]; bi = idxs[k]; }
#pragma unroll
        for (int off = 16; off; off >>= 1) {
            float ov = __shfl_xor_sync(0xffffffffu, bv, off);
            int   oi = __shfl_xor_sync(0xffffffffu, bi, off);
            if (ov > bv || (ov == bv && oi < bi)) { bv = ov; bi = oi; }
        }
#pragma unroll
        for (int k = 0; k < SLOTS; k++)
            if (idxs[k] == bi) vals[k] = -1.f;
        if (lane == 0) { swv[w][it] = bv; swi[w][it] = bi; }
    }
    __syncthreads();

    if (w == 0) {
        float mv[3]; int mi[3];
#pragma unroll
        for (int k = 0; k < 3; k++) {
            int j = lane + 32 * k;
            if (j < 96) { mv[k] = swv[j / KTOP][j % KTOP]; mi[k] = swi[j / KTOP][j % KTOP]; }
            else        { mv[k] = -1.f; mi[k] = INT_MAX; }
        }
        float myv = -1.f; int myi = 0;
        float sum = 0.f;
#pragma unroll
        for (int it = 0; it < KTOP; it++) {
            float bv = -1.f; int bi = INT_MAX;
#pragma unroll
            for (int k = 0; k < 3; k++)
                if (mv[k] > bv || (mv[k] == bv && mi[k] < bi)) { bv = mv[k]; bi = mi[k]; }
#pragma unroll
            for (int off = 16; off; off >>= 1) {
                float ov = __shfl_xor_sync(0xffffffffu, bv, off);
                int   oi = __shfl_xor_sync(0xffffffffu, bi, off);
                if (ov > bv || (ov == bv && oi < bi)) { bv = ov; bi = oi; }
            }
#pragma unroll
            for (int k = 0; k < 3; k++)
                if (mi[k] == bi) mv[k] = -1.f;
            if (lane == it) { myv = bv; myi = bi; }
            sum += bv;
        }
        float inv = 1.f / (1.f + sum);
        if (lane < KTOP) {
            g_nbr[v * NBRS + lane] = myi;
            g_nw [v * NBRS + lane] = myv * inv;
        }
        if (lane == 0) {
            g_nbr[v * NBRS + KTOP] = v;
            g_nw [v * NBRS + KTOP] = inv;
        }
    }
}

// ============ K2: folded inception temporal conv -> H0[N][b][c][t] ============
__device__ __forceinline__ constexpr int KC(int c) {
    return c < 4 ? 2 : (c < 8 ? 3 : (c < 12 ? 6 : 7));
}

__global__ void k_tconv(const float* __restrict__ x) {
    int n = blockIdx.x;
    int tid = threadIdx.x;                    // 192 threads
    __shared__ float xs[BATCH][T_IN];
    __shared__ float swv[128];
    __shared__ float sbv[16];
    for (int i = tid; i < BATCH * T_IN; i += 192) {
        int b = i / T_IN, t = i - b * T_IN;
        xs[b][t] = x[(size_t)(b * T_IN + t) * NNODE + n];
    }
    if (tid < 128) swv[tid] = g_weff[tid];
    if (tid < 16)  sbv[tid] = g_beff[tid];
    __syncthreads();
    if (tid >= TLEN) return;

    float wr[16][8];
#pragma unroll
    for (int c = 0; c < 16; c++) {
        const int k = KC(c);
#pragma unroll
        for (int j = 0; j < 8; j++)
            if (j < k) wr[c][j] = swv[c * 8 + j];
    }
    float bb[16];
#pragma unroll
    for (int c = 0; c < 16; c++) bb[c] = sbv[c];

    float* outp = g_H0 + (size_t)n * FDIM + tid;
#pragma unroll
    for (int b = 0; b < BATCH; b++) {
#pragma unroll
        for (int c = 0; c < 16; c++) {
            const int k = KC(c);
            float acc = bb[c];
#pragma unroll
            for (int j = 0; j < k; j++)
                acc = fmaf(wr[c][j], xs[b][tid + 7 - k + j], acc);
            outp[(size_t)(b * 16 + c) * TLEN] = fmaxf(acc, 0.f);
        }
    }
}

// ============ K3/K4: pure propagation P = Â·src, float4 L2 gathers ============
__global__ void k_spmm(const float* __restrict__ src, float* __restrict__ dst) {
    int v = blockIdx.x;
    int f4 = blockIdx.y * 192 + threadIdx.x;   // FDIM4=5184 = 27*192
    __shared__ int   nb[NBRS];
    __shared__ float nw[NBRS];
    if (threadIdx.x < NBRS) {
        nb[threadIdx.x] = g_nbr[v * NBRS + threadIdx.x];
        nw[threadIdx.x] = g_nw [v * NBRS + threadIdx.x];
    }
    __syncthreads();
    const float4* s4 = (const float4*)src;
    float4 acc = make_float4(0.f, 0.f, 0.f, 0.f);
#pragma unroll
    for (int j = 0; j < NBRS; j++) {
        float4 hv = s4[(size_t)nb[j] * FDIM4 + f4];
        float wj = nw[j];
        acc.x = fmaf(wj, hv.x, acc.x);
        acc.y = fmaf(wj, hv.y, acc.y);
        acc.z = fmaf(wj, hv.z, acc.z);
        acc.w = fmaf(wj, hv.w, acc.w);
    }
    ((float4*)dst)[(size_t)v * FDIM4 + f4] = acc;
}

// ============ K5: MLP head, folded G weights in SMEM, f32x2, 6 t's/thread ============
__global__ __launch_bounds__(224, 2) void k_final(
    const float* __restrict__ mb,
    const float* __restrict__ rw1, const float* __restrict__ rb1,
    const float* __restrict__ rw2, const float* __restrict__ rb2,
    float* __restrict__ out) {
    int v = blockIdx.x;
    int tid = threadIdx.x;                 // 224 threads; 216 active in main phase
    __shared__ float2 sg[768];             // G dup pairs: [j][s*16+c]
    __shared__ float2 sr1[256];            // rw1 dup pairs
    __shared__ float  s_mb[16], s_rb1[16], s_rw2[384], s_rb2[24];
    __shared__ float  part[216][16];
    __shared__ float  rm[8][16];

    for (int idx = tid; idx < 768; idx += 224) { float w = g_G[idx]; sg[idx]  = make_float2(w, w); }
    for (int idx = tid; idx < 256; idx += 224) { float w = rw1[idx]; sr1[idx] = make_float2(w, w); }
    for (int idx = tid; idx < 384; idx += 224) s_rw2[idx] = rw2[idx];
    if (tid < 16) { s_mb[tid] = mb[tid]; s_rb1[tid] = rb1[tid]; }
    if (tid < 24) s_rb2[tid] = rb2[tid];
    __syncthreads();

    if (tid < 216) {
        int b = tid / 27;
        int i = tid - b * 27;
        int t0 = i * 6;                    // 27*6 = 162 exactly
        size_t off = (size_t)v * FDIM + (size_t)b * (CH * TLEN) + t0;

        float2 z0[16], z1[16], z2[16];
#pragma unroll
        for (int j = 0; j < 16; j++) {
            float m = s_mb[j];
            z0[j] = make_float2(m, m); z1[j] = z0[j]; z2[j] = z0[j];
        }

#pragma unroll
        for (int s = 0; s < 3; s++) {
            const float* bp = (s == 0 ? g_H0 : (s == 1 ? g_P1 : g_P2)) + off;
#pragma unroll
            for (int c = 0; c < 16; c++) {
                const float* p = bp + (size_t)c * TLEN;
                float2 h0 = *reinterpret_cast<const float2*>(p);
                float2 h1 = *reinterpret_cast<const float2*>(p + 2);
                float2 h2 = *reinterpret_cast<const float2*>(p + 4);
#pragma unroll
                for (int j = 0; j < 16; j++) {
                    float2 w = sg[j * 48 + s * 16 + c];
                    z0[j] = ffma2(w, h0, z0[j]);
                    z1[j] = ffma2(w, h1, z1[j]);
                    z2[j] = ffma2(w, h2, z2[j]);
                }
            }
        }

#pragma unroll
        for (int j = 0; j < 16; j++) {
            z0[j].x = fmaxf(z0[j].x, 0.f); z0[j].y = fmaxf(z0[j].y, 0.f);
            z1[j].x = fmaxf(z1[j].x, 0.f); z1[j].y = fmaxf(z1[j].y, 0.f);
            z2[j].x = fmaxf(z2[j].x, 0.f); z2[j].y = fmaxf(z2[j].y, 0.f);
        }

#pragma unroll
        for (int i2 = 0; i2 < 16; i2++) {
            float rb = s_rb1[i2];
            float2 a0 = make_float2(rb, rb), a1 = a0, a2 = a0;
#pragma unroll
            for (int j = 0; j < 16; j++) {
                float2 w = sr1[i2 * 16 + j];
                a0 = ffma2(w, z0[j], a0);
                a1 = ffma2(w, z1[j], a1);
                a2 = ffma2(w, z2[j], a2);
            }
            part[tid][i2] = fmaxf(a0.x, 0.f) + fmaxf(a0.y, 0.f)
                          + fmaxf(a1.x, 0.f) + fmaxf(a1.y, 0.f)
                          + fmaxf(a2.x, 0.f) + fmaxf(a2.y, 0.f);
        }
    }
    __syncthreads();

    if (tid < 128) {
        int b = tid >> 4, i = tid & 15;
        float s = 0.f;
#pragma unroll
        for (int k = 0; k < 27; k++) s += part[b * 27 + k][i];
        rm[b][i] = s * (1.f / (float)TLEN);
    }
    __syncthreads();

    if (tid < 192) {
        int b = tid / 24, o = tid - b * 24;
        float a = s_rb2[o];
#pragma unroll
        for (int c = 0; c < 16; c++) a += s_rw2[o * 16 + c] * rm[b][c];
        out[((size_t)b * 24 + o) * NNODE + v] = a;
    }
}

// ======================= launcher =======================
extern "C" void kernel_launch(void* const* d_in, const int* in_sizes, int n_in,
                              void* d_out, int out_size) {
    const float* x   = (const float*)d_in[0];
    const float* pw  = (const float*)d_in[1];
    const float* pb  = (const float*)d_in[2];
    const float* tw2 = (const float*)d_in[3];
    const float* tb2 = (const float*)d_in[4];
    const float* tw3 = (const float*)d_in[5];
    const float* tb3 = (const float*)d_in[6];
    const float* tw6 = (const float*)d_in[7];
    const float* tb6 = (const float*)d_in[8];
    const float* tw7 = (const float*)d_in[9];
    const float* tb7 = (const float*)d_in[10];
    const float* e1  = (const float*)d_in[11];
    const float* e2  = (const float*)d_in[12];
    const float* gw1 = (const float*)d_in[13];
    const float* gb1 = (const float*)d_in[14];
    const float* gw2 = (const float*)d_in[15];
    const float* gb2 = (const float*)d_in[16];
    const float* mw  = (const float*)d_in[17];
    const float* mb  = (const float*)d_in[18];
    const float* rw1 = (const float*)d_in[19];
    const float* rb1 = (const float*)d_in[20];
    const float* rw2 = (const float*)d_in[21];
    const float* rb2 = (const float*)d_in[22];

    float* H0 = nullptr; float* P1 = nullptr; float* P2 = nullptr;
    cudaGetSymbolAddress((void**)&H0, g_H0);
    cudaGetSymbolAddress((void**)&P1, g_P1);
    cudaGetSymbolAddress((void**)&P2, g_P2);

    k_prep<<<(NNODE + 127) / 128, 128>>>(pw, pb, tw2, tb2, tw3, tb3, tw6, tb6, tw7, tb7,
                                         e1, gw1, gb1, e2, gw2, gb2, mw);
    k_topk<<<NNODE, 256>>>();
    k_tconv<<<NNODE, 192>>>(x);

    dim3 gs(NNODE, FDIM4 / 192);   // 1500 x 27
    k_spmm<<<gs, 192>>>(H0, P1);   // 4th launch -> profiled
    k_spmm<<<gs, 192>>>(P1, P2);

    k_final<<<NNODE, 224>>>(mb, rw1, rb1, rw2, rb2, (float*)d_out);
}

// round 12
// speedup vs baseline: 1.9224x; 1.2387x over previous
#include <cuda_runtime.h>
#include <cuda_fp16.h>
#include <cstdint>
#include <cstddef>
#include <climits>

#define NNODE 1500
#define T_IN  168
#define TLEN  162
#define BATCH 8
#define CH    16
#define EMBD  16
#define KTOP  12
#define NBRS  13            // KTOP + self
#define FDIM  (BATCH*CH*TLEN)   // 20736
#define FDIM8 (FDIM/8)          // 2592 = 27*96
#define ALPHA 1.5f
#define BETA  0.2f

// ---------------- device scratch (no allocations allowed) ----------------
__device__ __half g_H0[(size_t)NNODE * FDIM];
__device__ __half g_P1[(size_t)NNODE * FDIM];
__device__ __half g_P2[(size_t)NNODE * FDIM];
__device__ float g_m1[NNODE * EMBD];
__device__ float g_m2[NNODE * EMBD];
__device__ float g_weff[CH * 8];
__device__ float g_beff[CH];
__device__ int   g_nbr[NNODE * NBRS];
__device__ float g_nw [NNODE * NBRS];
__device__ float g_G[768];          // folded 48->16 weights [j][s*16+c]

// ---------------- packed fp32x2 FMA (sm_103a FFMA2) ----------------
__device__ __forceinline__ float2 ffma2(float2 a, float2 b, float2 c) {
    unsigned long long au = *reinterpret_cast<unsigned long long*>(&a);
    unsigned long long bu = *reinterpret_cast<unsigned long long*>(&b);
    unsigned long long cu = *reinterpret_cast<unsigned long long*>(&c);
    unsigned long long du;
    asm("fma.rn.f32x2 %0, %1, %2, %3;" : "=l"(du) : "l"(au), "l"(bu), "l"(cu));
    return *reinterpret_cast<float2*>(&du);
}

// ============ K0: combined prep (weff fold + embeddings + G fold) ============
__global__ void k_prep(const float* pw, const float* pb,
                       const float* tw2, const float* tb2,
                       const float* tw3, const float* tb3,
                       const float* tw6, const float* tb6,
                       const float* tw7, const float* tb7,
                       const float* e1, const float* gw1, const float* gb1,
                       const float* e2, const float* gw2, const float* gb2,
                       const float* mw) {
    int n = blockIdx.x * 128 + threadIdx.x;
    if (n < NNODE) {
        float ev1[EMBD], ev2[EMBD];
#pragma unroll
        for (int i = 0; i < EMBD; i++) { ev1[i] = e1[n * EMBD + i]; ev2[i] = e2[n * EMBD + i]; }
#pragma unroll
        for (int e = 0; e < EMBD; e++) {
            float a1 = gb1[e], a2 = gb2[e];
#pragma unroll
            for (int k = 0; k < EMBD; k++) {
                a1 += ev1[k] * gw1[k * EMBD + e];
                a2 += ev2[k] * gw2[k * EMBD + e];
            }
            g_m1[n * EMBD + e] = tanhf(ALPHA * a1);
            g_m2[n * EMBD + e] = tanhf(ALPHA * a2);
        }
    }
    if (blockIdx.x == 0) {
        if (threadIdx.x < CH) {
            int c = threadIdx.x;
            int br = c >> 2, o = c & 3;
            const float* tw; const float* tb; int k;
            if      (br == 0) { tw = tw2; tb = tb2; k = 2; }
            else if (br == 1) { tw = tw3; tb = tb3; k = 3; }
            else if (br == 2) { tw = tw6; tb = tb6; k = 6; }
            else              { tw = tw7; tb = tb7; k = 7; }
            float bacc = tb[o];
            for (int j = 0; j < k; j++) {
                float wacc = 0.f;
                for (int ci = 0; ci < CH; ci++) {
                    float w = tw[(o * CH + ci) * k + j];
                    wacc += w * pw[ci];
                    bacc += w * pb[ci];
                }
                g_weff[c * 8 + j] = wacc;
            }
            g_beff[c] = bacc;
        }
        // folded 48->16 layer: z = G0*H0 + G1*P1 + G2*P2
        for (int idx = threadIdx.x; idx < 768; idx += 128) {
            int j = idx / 48, c = idx % 48;
            int hop = c >> 4, ci = c & 15;
            const float* row = mw + j * 48;
            float m1v = row[16 + ci], m2v = row[32 + ci];
            float g;
            if      (hop == 0) g = row[ci] + BETA * m1v + BETA * m2v;
            else if (hop == 1) g = (1.f - BETA) * m1v + BETA * (1.f - BETA) * m2v;
            else               g = (1.f - BETA) * (1.f - BETA) * m2v;
            g_G[idx] = g;
        }
    }
}

// ============ K1: warp-level tournament top-12 (no barriers in hot loop) ============
#define SEG 188                       // ceil(1500 / 8)
#define SLOTS 6                       // ceil(SEG / 32)

__global__ void k_topk() {
    int v = blockIdx.x;
    int tid = threadIdx.x;            // 256 threads, 8 warps
    int w = tid >> 5, lane = tid & 31;

    float m1v[EMBD], m2v[EMBD];
#pragma unroll
    for (int e = 0; e < EMBD; e++) { m1v[e] = g_m1[v * EMBD + e]; m2v[e] = g_m2[v * EMBD + e]; }

    int base = w * SEG;
    int segEnd = min(base + SEG, NNODE);
    float vals[SLOTS];
    int   idxs[SLOTS];
#pragma unroll
    for (int k = 0; k < SLOTS; k++) {
        int idx = base + k * 32 + lane;
        if (idx < segEnd) {
            const float4* p2 = (const float4*)(g_m2 + idx * EMBD);
            const float4* p1 = (const float4*)(g_m1 + idx * EMBD);
            float d = 0.f;
#pragma unroll
            for (int q = 0; q < 4; q++) {
                float4 a2 = p2[q], a1 = p1[q];
                d += m1v[4*q+0]*a2.x - m2v[4*q+0]*a1.x;
                d += m1v[4*q+1]*a2.y - m2v[4*q+1]*a1.y;
                d += m1v[4*q+2]*a2.z - m2v[4*q+2]*a1.z;
                d += m1v[4*q+3]*a2.w - m2v[4*q+3]*a1.w;
            }
            float a = tanhf(ALPHA * d);
            vals[k] = a > 0.f ? a : 0.f;
            idxs[k] = idx;
        } else {
            vals[k] = -1.f;
            idxs[k] = INT_MAX;
        }
    }

    __shared__ float swv[8][KTOP];
    __shared__ int   swi[8][KTOP];

#pragma unroll
    for (int it = 0; it < KTOP; it++) {
        float bv = -1.f; int bi = INT_MAX;
#pragma unroll
        for (int k = 0; k < SLOTS; k++)
            if (vals[k] > bv || (vals[k] == bv && idxs[k] < bi)) { bv = vals[k]; bi = idxs[k]; }
#pragma unroll
        for (int off = 16; off; off >>= 1) {
            float ov = __shfl_xor_sync(0xffffffffu, bv, off);
            int   oi = __shfl_xor_sync(0xffffffffu, bi, off);
            if (ov > bv || (ov == bv && oi < bi)) { bv = ov; bi = oi; }
        }
#pragma unroll
        for (int k = 0; k < SLOTS; k++)
            if (idxs[k] == bi) vals[k] = -1.f;
        if (lane == 0) { swv[w][it] = bv; swi[w][it] = bi; }
    }
    __syncthreads();

    if (w == 0) {
        float mv[3]; int mi[3];
#pragma unroll
        for (int k = 0; k < 3; k++) {
            int j = lane + 32 * k;
            if (j < 96) { mv[k] = swv[j / KTOP][j % KTOP]; mi[k] = swi[j / KTOP][j % KTOP]; }
            else        { mv[k] = -1.f; mi[k] = INT_MAX; }
        }
        float myv = -1.f; int myi = 0;
        float sum = 0.f;
#pragma unroll
        for (int it = 0; it < KTOP; it++) {
            float bv = -1.f; int bi = INT_MAX;
#pragma unroll
            for (int k = 0; k < 3; k++)
                if (mv[k] > bv || (mv[k] == bv && mi[k] < bi)) { bv = mv[k]; bi = mi[k]; }
#pragma unroll
            for (int off = 16; off; off >>= 1) {
                float ov = __shfl_xor_sync(0xffffffffu, bv, off);
                int   oi = __shfl_xor_sync(0xffffffffu, bi, off);
                if (ov > bv || (ov == bv && oi < bi)) { bv = ov; bi = oi; }
            }
#pragma unroll
            for (int k = 0; k < 3; k++)
                if (mi[k] == bi) mv[k] = -1.f;
            if (lane == it) { myv = bv; myi = bi; }
            sum += bv;
        }
        float inv = 1.f / (1.f + sum);
        if (lane < KTOP) {
            g_nbr[v * NBRS + lane] = myi;
            g_nw [v * NBRS + lane] = myv * inv;
        }
        if (lane == 0) {
            g_nbr[v * NBRS + KTOP] = v;
            g_nw [v * NBRS + KTOP] = inv;
        }
    }
}

// ============ K2: folded inception temporal conv -> H0[N][b][c][t] (fp16) ============
__device__ __forceinline__ constexpr int KC(int c) {
    return c < 4 ? 2 : (c < 8 ? 3 : (c < 12 ? 6 : 7));
}

__global__ void k_tconv(const float* __restrict__ x) {
    int n = blockIdx.x;
    int tid = threadIdx.x;                    // 192 threads
    __shared__ float xs[BATCH][T_IN];
    __shared__ float swv[128];
    __shared__ float sbv[16];
    for (int i = tid; i < BATCH * T_IN; i += 192) {
        int b = i / T_IN, t = i - b * T_IN;
        xs[b][t] = x[(size_t)(b * T_IN + t) * NNODE + n];
    }
    if (tid < 128) swv[tid] = g_weff[tid];
    if (tid < 16)  sbv[tid] = g_beff[tid];
    __syncthreads();
    if (tid >= TLEN) return;

    float wr[16][8];
#pragma unroll
    for (int c = 0; c < 16; c++) {
        const int k = KC(c);
#pragma unroll
        for (int j = 0; j < 8; j++)
            if (j < k) wr[c][j] = swv[c * 8 + j];
    }
    float bb[16];
#pragma unroll
    for (int c = 0; c < 16; c++) bb[c] = sbv[c];

    __half* outp = g_H0 + (size_t)n * FDIM + tid;
#pragma unroll
    for (int b = 0; b < BATCH; b++) {
#pragma unroll
        for (int c = 0; c < 16; c++) {
            const int k = KC(c);
            float acc = bb[c];
#pragma unroll
            for (int j = 0; j < k; j++)
                acc = fmaf(wr[c][j], xs[b][tid + 7 - k + j], acc);
            outp[(size_t)(b * 16 + c) * TLEN] = __float2half(fmaxf(acc, 0.f));
        }
    }
}

// ============ K3/K4: pure propagation P = Â·src, uint4 (8-half) L2 gathers ============
__global__ void k_spmm(const __half* __restrict__ src, __half* __restrict__ dst) {
    int v = blockIdx.x;
    int f8 = blockIdx.y * 96 + threadIdx.x;   // FDIM8=2592 = 27*96
    __shared__ int   nb[NBRS];
    __shared__ float nw[NBRS];
    if (threadIdx.x < NBRS) {
        nb[threadIdx.x] = g_nbr[v * NBRS + threadIdx.x];
        nw[threadIdx.x] = g_nw [v * NBRS + threadIdx.x];
    }
    __syncthreads();
    const uint4* s8 = (const uint4*)src;
    float2 a0 = make_float2(0.f, 0.f), a1 = a0, a2 = a0, a3 = a0;
#pragma unroll
    for (int j = 0; j < NBRS; j++) {
        uint4 hv = s8[(size_t)nb[j] * FDIM8 + f8];
        float wj = nw[j];
        float2 w2 = make_float2(wj, wj);
        const half2* h = (const half2*)&hv;
        a0 = ffma2(w2, __half22float2(h[0]), a0);
        a1 = ffma2(w2, __half22float2(h[1]), a1);
        a2 = ffma2(w2, __half22float2(h[2]), a2);
        a3 = ffma2(w2, __half22float2(h[3]), a3);
    }
    uint4 r;
    ((half2*)&r)[0] = __float22half2_rn(a0);
    ((half2*)&r)[1] = __float22half2_rn(a1);
    ((half2*)&r)[2] = __float22half2_rn(a2);
    ((half2*)&r)[3] = __float22half2_rn(a3);
    ((uint4*)dst)[(size_t)v * FDIM8 + f8] = r;
}

// ============ K5: MLP head, folded G weights in SMEM, f32x2, 6 t's/thread ============
__global__ __launch_bounds__(224, 2) void k_final(
    const float* __restrict__ mb,
    const float* __restrict__ rw1, const float* __restrict__ rb1,
    const float* __restrict__ rw2, const float* __restrict__ rb2,
    float* __restrict__ out) {
    int v = blockIdx.x;
    int tid = threadIdx.x;                 // 224 threads; 216 active in main phase
    __shared__ float2 sg[768];             // G dup pairs: [j][s*16+c]
    __shared__ float2 sr1[256];            // rw1 dup pairs
    __shared__ float  s_mb[16], s_rb1[16], s_rw2[384], s_rb2[24];
    __shared__ float  part[216][16];
    __shared__ float  rm[8][16];

    for (int idx = tid; idx < 768; idx += 224) { float w = g_G[idx]; sg[idx]  = make_float2(w, w); }
    for (int idx = tid; idx < 256; idx += 224) { float w = rw1[idx]; sr1[idx] = make_float2(w, w); }
    for (int idx = tid; idx < 384; idx += 224) s_rw2[idx] = rw2[idx];
    if (tid < 16) { s_mb[tid] = mb[tid]; s_rb1[tid] = rb1[tid]; }
    if (tid < 24) s_rb2[tid] = rb2[tid];
    __syncthreads();

    if (tid < 216) {
        int b = tid / 27;
        int i = tid - b * 27;
        int t0 = i * 6;                    // 27*6 = 162 exactly
        size_t off = (size_t)v * FDIM + (size_t)b * (CH * TLEN) + t0;

        float2 z0[16], z1[16], z2[16];
#pragma unroll
        for (int j = 0; j < 16; j++) {
            float m = s_mb[j];
            z0[j] = make_float2(m, m); z1[j] = z0[j]; z2[j] = z0[j];
        }

#pragma unroll
        for (int s = 0; s < 3; s++) {
            const __half* bp = (s == 0 ? g_H0 : (s == 1 ? g_P1 : g_P2)) + off;
#pragma unroll
            for (int c = 0; c < 16; c++) {
                const __half* p = bp + (size_t)c * TLEN;
                float2 h0 = __half22float2(*reinterpret_cast<const half2*>(p));
                float2 h1 = __half22float2(*reinterpret_cast<const half2*>(p + 2));
                float2 h2 = __half22float2(*reinterpret_cast<const half2*>(p + 4));
#pragma unroll
                for (int j = 0; j < 16; j++) {
                    float2 w = sg[j * 48 + s * 16 + c];
                    z0[j] = ffma2(w, h0, z0[j]);
                    z1[j] = ffma2(w, h1, z1[j]);
                    z2[j] = ffma2(w, h2, z2[j]);
                }
            }
        }

#pragma unroll
        for (int j = 0; j < 16; j++) {
            z0[j].x = fmaxf(z0[j].x, 0.f); z0[j].y = fmaxf(z0[j].y, 0.f);
            z1[j].x = fmaxf(z1[j].x, 0.f); z1[j].y = fmaxf(z1[j].y, 0.f);
            z2[j].x = fmaxf(z2[j].x, 0.f); z2[j].y = fmaxf(z2[j].y, 0.f);
        }

#pragma unroll
        for (int i2 = 0; i2 < 16; i2++) {
            float rb = s_rb1[i2];
            float2 a0 = make_float2(rb, rb), a1 = a0, a2 = a0;
#pragma unroll
            for (int j = 0; j < 16; j++) {
                float2 w = sr1[i2 * 16 + j];
                a0 = ffma2(w, z0[j], a0);
                a1 = ffma2(w, z1[j], a1);
                a2 = ffma2(w, z2[j], a2);
            }
            part[tid][i2] = fmaxf(a0.x, 0.f) + fmaxf(a0.y, 0.f)
                          + fmaxf(a1.x, 0.f) + fmaxf(a1.y, 0.f)
                          + fmaxf(a2.x, 0.f) + fmaxf(a2.y, 0.f);
        }
    }
    __syncthreads();

    if (tid < 128) {
        int b = tid >> 4, i = tid & 15;
        float s = 0.f;
#pragma unroll
        for (int k = 0; k < 27; k++) s += part[b * 27 + k][i];
        rm[b][i] = s * (1.f / (float)TLEN);
    }
    __syncthreads();

    if (tid < 192) {
        int b = tid / 24, o = tid - b * 24;
        float a = s_rb2[o];
#pragma unroll
        for (int c = 0; c < 16; c++) a += s_rw2[o * 16 + c] * rm[b][c];
        out[((size_t)b * 24 + o) * NNODE + v] = a;
    }
}

// ======================= launcher =======================
extern "C" void kernel_launch(void* const* d_in, const int* in_sizes, int n_in,
                              void* d_out, int out_size) {
    const float* x   = (const float*)d_in[0];
    const float* pw  = (const float*)d_in[1];
    const float* pb  = (const float*)d_in[2];
    const float* tw2 = (const float*)d_in[3];
    const float* tb2 = (const float*)d_in[4];
    const float* tw3 = (const float*)d_in[5];
    const float* tb3 = (const float*)d_in[6];
    const float* tw6 = (const float*)d_in[7];
    const float* tb6 = (const float*)d_in[8];
    const float* tw7 = (const float*)d_in[9];
    const float* tb7 = (const float*)d_in[10];
    const float* e1  = (const float*)d_in[11];
    const float* e2  = (const float*)d_in[12];
    const float* gw1 = (const float*)d_in[13];
    const float* gb1 = (const float*)d_in[14];
    const float* gw2 = (const float*)d_in[15];
    const float* gb2 = (const float*)d_in[16];
    const float* mw  = (const float*)d_in[17];
    const float* mb  = (const float*)d_in[18];
    const float* rw1 = (const float*)d_in[19];
    const float* rb1 = (const float*)d_in[20];
    const float* rw2 = (const float*)d_in[21];
    const float* rb2 = (const float*)d_in[22];

    __half* H0 = nullptr; __half* P1 = nullptr; __half* P2 = nullptr;
    cudaGetSymbolAddress((void**)&H0, g_H0);
    cudaGetSymbolAddress((void**)&P1, g_P1);
    cudaGetSymbolAddress((void**)&P2, g_P2);

    k_prep<<<(NNODE + 127) / 128, 128>>>(pw, pb, tw2, tb2, tw3, tb3, tw6, tb6, tw7, tb7,
                                         e1, gw1, gb1, e2, gw2, gb2, mw);
    k_topk<<<NNODE, 256>>>();
    k_tconv<<<NNODE, 192>>>(x);

    dim3 gs(NNODE, FDIM8 / 96);    // 1500 x 27
    k_spmm<<<gs, 96>>>(H0, P1);    // 4th launch -> profiled
    k_spmm<<<gs, 96>>>(P1, P2);

    k_final<<<NNODE, 224>>>(mb, rw1, rb1, rw2, rb2, (float*)d_out);
}

// round 16
// speedup vs baseline: 2.3461x; 1.2204x over previous
#include <cuda_runtime.h>
#include <cuda_fp16.h>
#include <cstdint>
#include <cstddef>
#include <climits>

#define NNODE 1500
#define T_IN  168
#define TLEN  162
#define BATCH 8
#define CH    16
#define EMBD  16
#define KTOP  12
#define NBRS  13            // KTOP + self
#define FDIM  (BATCH*CH*TLEN)   // 20736
#define FDIM8 (FDIM/8)          // 2592 = 27*96
#define ALPHA 1.5f
#define BETA  0.2f

// H-state layout: idx(v,b,t,c) = v*FDIM + (b*TLEN + t)*CH + c   (c innermost)
__device__ __half g_H0[(size_t)NNODE * FDIM];
__device__ __half g_P1[(size_t)NNODE * FDIM];
__device__ __half g_P2[(size_t)NNODE * FDIM];
__device__ float g_m1[NNODE * EMBD];
__device__ float g_m2[NNODE * EMBD];
__device__ float g_weff[CH * 8];
__device__ float g_beff[CH];
__device__ int   g_nbr[NNODE * NBRS];
__device__ float g_nw [NNODE * NBRS];
__device__ float g_G[768];          // folded 48->16 weights [j][s*16+c]

// ---------------- packed fp32x2 FMA (sm_103a FFMA2) ----------------
__device__ __forceinline__ float2 ffma2(float2 a, float2 b, float2 c) {
    unsigned long long au = *reinterpret_cast<unsigned long long*>(&a);
    unsigned long long bu = *reinterpret_cast<unsigned long long*>(&b);
    unsigned long long cu = *reinterpret_cast<unsigned long long*>(&c);
    unsigned long long du;
    asm("fma.rn.f32x2 %0, %1, %2, %3;" : "=l"(du) : "l"(au), "l"(bu), "l"(cu));
    return *reinterpret_cast<float2*>(&du);
}

// ============ K0: combined prep (weff fold + embeddings + G fold) ============
__global__ void k_prep(const float* pw, const float* pb,
                       const float* tw2, const float* tb2,
                       const float* tw3, const float* tb3,
                       const float* tw6, const float* tb6,
                       const float* tw7, const float* tb7,
                       const float* e1, const float* gw1, const float* gb1,
                       const float* e2, const float* gw2, const float* gb2,
                       const float* mw) {
    int n = blockIdx.x * 128 + threadIdx.x;
    if (n < NNODE) {
        float ev1[EMBD], ev2[EMBD];
#pragma unroll
        for (int i = 0; i < EMBD; i++) { ev1[i] = e1[n * EMBD + i]; ev2[i] = e2[n * EMBD + i]; }
#pragma unroll
        for (int e = 0; e < EMBD; e++) {
            float a1 = gb1[e], a2 = gb2[e];
#pragma unroll
            for (int k = 0; k < EMBD; k++) {
                a1 += ev1[k] * gw1[k * EMBD + e];
                a2 += ev2[k] * gw2[k * EMBD + e];
            }
            g_m1[n * EMBD + e] = tanhf(ALPHA * a1);
            g_m2[n * EMBD + e] = tanhf(ALPHA * a2);
        }
    }
    if (blockIdx.x == 0) {
        if (threadIdx.x < CH) {
            int c = threadIdx.x;
            int br = c >> 2, o = c & 3;
            const float* tw; const float* tb; int k;
            if      (br == 0) { tw = tw2; tb = tb2; k = 2; }
            else if (br == 1) { tw = tw3; tb = tb3; k = 3; }
            else if (br == 2) { tw = tw6; tb = tb6; k = 6; }
            else              { tw = tw7; tb = tb7; k = 7; }
            float bacc = tb[o];
            for (int j = 0; j < k; j++) {
                float wacc = 0.f;
                for (int ci = 0; ci < CH; ci++) {
                    float w = tw[(o * CH + ci) * k + j];
                    wacc += w * pw[ci];
                    bacc += w * pb[ci];
                }
                g_weff[c * 8 + j] = wacc;
            }
            g_beff[c] = bacc;
        }
        for (int idx = threadIdx.x; idx < 768; idx += 128) {
            int j = idx / 48, c = idx % 48;
            int hop = c >> 4, ci = c & 15;
            const float* row = mw + j * 48;
            float m1v = row[16 + ci], m2v = row[32 + ci];
            float g;
            if      (hop == 0) g = row[ci] + BETA * m1v + BETA * m2v;
            else if (hop == 1) g = (1.f - BETA) * m1v + BETA * (1.f - BETA) * m2v;
            else               g = (1.f - BETA) * (1.f - BETA) * m2v;
            g_G[idx] = g;
        }
    }
}

// ============ K1: warp-level tournament top-12 (no barriers in hot loop) ============
#define SEG 188
#define SLOTS 6

__global__ void k_topk() {
    int v = blockIdx.x;
    int tid = threadIdx.x;
    int w = tid >> 5, lane = tid & 31;

    float m1v[EMBD], m2v[EMBD];
#pragma unroll
    for (int e = 0; e < EMBD; e++) { m1v[e] = g_m1[v * EMBD + e]; m2v[e] = g_m2[v * EMBD + e]; }

    int base = w * SEG;
    int segEnd = min(base + SEG, NNODE);
    float vals[SLOTS];
    int   idxs[SLOTS];
#pragma unroll
    for (int k = 0; k < SLOTS; k++) {
        int idx = base + k * 32 + lane;
        if (idx < segEnd) {
            const float4* p2 = (const float4*)(g_m2 + idx * EMBD);
            const float4* p1 = (const float4*)(g_m1 + idx * EMBD);
            float d = 0.f;
#pragma unroll
            for (int q = 0; q < 4; q++) {
                float4 a2 = p2[q], a1 = p1[q];
                d += m1v[4*q+0]*a2.x - m2v[4*q+0]*a1.x;
                d += m1v[4*q+1]*a2.y - m2v[4*q+1]*a1.y;
                d += m1v[4*q+2]*a2.z - m2v[4*q+2]*a1.z;
                d += m1v[4*q+3]*a2.w - m2v[4*q+3]*a1.w;
            }
            float a = tanhf(ALPHA * d);
            vals[k] = a > 0.f ? a : 0.f;
            idxs[k] = idx;
        } else {
            vals[k] = -1.f;
            idxs[k] = INT_MAX;
        }
    }

    __shared__ float swv[8][KTOP];
    __shared__ int   swi[8][KTOP];

#pragma unroll
    for (int it = 0; it < KTOP; it++) {
        float bv = -1.f; int bi = INT_MAX;
#pragma unroll
        for (int k = 0; k < SLOTS; k++)
            if (vals[k] > bv || (vals[k] == bv && idxs[k] < bi)) { bv = vals[k]; bi = idxs[k]; }
#pragma unroll
        for (int off = 16; off; off >>= 1) {
            float ov = __shfl_xor_sync(0xffffffffu, bv, off);
            int   oi = __shfl_xor_sync(0xffffffffu, bi, off);
            if (ov > bv || (ov == bv && oi < bi)) { bv = ov; bi = oi; }
        }
#pragma unroll
        for (int k = 0; k < SLOTS; k++)
            if (idxs[k] == bi) vals[k] = -1.f;
        if (lane == 0) { swv[w][it] = bv; swi[w][it] = bi; }
    }
    __syncthreads();

    if (w == 0) {
        float mv[3]; int mi[3];
#pragma unroll
        for (int k = 0; k < 3; k++) {
            int j = lane + 32 * k;
            if (j < 96) { mv[k] = swv[j / KTOP][j % KTOP]; mi[k] = swi[j / KTOP][j % KTOP]; }
            else        { mv[k] = -1.f; mi[k] = INT_MAX; }
        }
        float myv = -1.f; int myi = 0;
        float sum = 0.f;
#pragma unroll
        for (int it = 0; it < KTOP; it++) {
            float bv = -1.f; int bi = INT_MAX;
#pragma unroll
            for (int k = 0; k < 3; k++)
                if (mv[k] > bv || (mv[k] == bv && mi[k] < bi)) { bv = mv[k]; bi = mi[k]; }
#pragma unroll
            for (int off = 16; off; off >>= 1) {
                float ov = __shfl_xor_sync(0xffffffffu, bv, off);
                int   oi = __shfl_xor_sync(0xffffffffu, bi, off);
                if (ov > bv || (ov == bv && oi < bi)) { bv = ov; bi = oi; }
            }
#pragma unroll
            for (int k = 0; k < 3; k++)
                if (mi[k] == bi) mv[k] = -1.f;
            if (lane == it) { myv = bv; myi = bi; }
            sum += bv;
        }
        float inv = 1.f / (1.f + sum);
        if (lane < KTOP) {
            g_nbr[v * NBRS + lane] = myi;
            g_nw [v * NBRS + lane] = myv * inv;
        }
        if (lane == 0) {
            g_nbr[v * NBRS + KTOP] = v;
            g_nw [v * NBRS + KTOP] = inv;
        }
    }
}

// ============ K2: folded inception temporal conv -> H0[v][b][t][c] (fp16, coalesced) ============
__device__ __forceinline__ constexpr int KC(int c) {
    return c < 4 ? 2 : (c < 8 ? 3 : (c < 12 ? 6 : 7));
}

__global__ void k_tconv(const float* __restrict__ x) {
    int n = blockIdx.x;
    int tid = threadIdx.x;                    // 192 threads
    __shared__ float xs[BATCH][T_IN];
    __shared__ float swv[128];
    __shared__ float sbv[16];
    for (int i = tid; i < BATCH * T_IN; i += 192) {
        int b = i / T_IN, t = i - b * T_IN;
        xs[b][t] = x[(size_t)(b * T_IN + t) * NNODE + n];
    }
    if (tid < 128) swv[tid] = g_weff[tid];
    if (tid < 16)  sbv[tid] = g_beff[tid];
    __syncthreads();
    if (tid >= TLEN) return;

    float wr[16][8];
#pragma unroll
    for (int c = 0; c < 16; c++) {
        const int k = KC(c);
#pragma unroll
        for (int j = 0; j < 8; j++)
            if (j < k) wr[c][j] = swv[c * 8 + j];
    }
    float bb[16];
#pragma unroll
    for (int c = 0; c < 16; c++) bb[c] = sbv[c];

    __half* outp = g_H0 + (size_t)n * FDIM;
#pragma unroll
    for (int b = 0; b < BATCH; b++) {
        half2 pk[8];
#pragma unroll
        for (int q = 0; q < 8; q++) {
            float accs[2];
#pragma unroll
            for (int h = 0; h < 2; h++) {
                int c = 2 * q + h;
                const int k = KC(c);
                float acc = bb[c];
#pragma unroll
                for (int j = 0; j < k; j++)
                    acc = fmaf(wr[c][j], xs[b][tid + 7 - k + j], acc);
                accs[h] = fmaxf(acc, 0.f);
            }
            pk[q] = __floats2half2_rn(accs[0], accs[1]);
        }
        uint4* dst = (uint4*)(outp + ((size_t)b * TLEN + tid) * CH);
        dst[0] = ((uint4*)pk)[0];
        dst[1] = ((uint4*)pk)[1];
    }
}

// ============ K3/K4: pure propagation P = Â·src, uint4 (8-half) L2 gathers ============
__global__ void k_spmm(const __half* __restrict__ src, __half* __restrict__ dst) {
    int v = blockIdx.x;
    int f8 = blockIdx.y * 96 + threadIdx.x;   // FDIM8=2592 = 27*96
    __shared__ int   nb[NBRS];
    __shared__ float nw[NBRS];
    if (threadIdx.x < NBRS) {
        nb[threadIdx.x] = g_nbr[v * NBRS + threadIdx.x];
        nw[threadIdx.x] = g_nw [v * NBRS + threadIdx.x];
    }
    __syncthreads();
    const uint4* s8 = (const uint4*)src;
    float2 a0 = make_float2(0.f, 0.f), a1 = a0, a2 = a0, a3 = a0;
#pragma unroll
    for (int j = 0; j < NBRS; j++) {
        uint4 hv = s8[(size_t)nb[j] * FDIM8 + f8];
        float wj = nw[j];
        float2 w2 = make_float2(wj, wj);
        const half2* h = (const half2*)&hv;
        a0 = ffma2(w2, __half22float2(h[0]), a0);
        a1 = ffma2(w2, __half22float2(h[1]), a1);
        a2 = ffma2(w2, __half22float2(h[2]), a2);
        a3 = ffma2(w2, __half22float2(h[3]), a3);
    }
    uint4 r;
    ((half2*)&r)[0] = __float22half2_rn(a0);
    ((half2*)&r)[1] = __float22half2_rn(a1);
    ((half2*)&r)[2] = __float22half2_rn(a2);
    ((half2*)&r)[3] = __float22half2_rn(a3);
    ((uint4*)dst)[(size_t)v * FDIM8 + f8] = r;
}

// ============ K5: MLP head; thin threads (1 t-pair), [b][t][c] layout ============
__global__ __launch_bounds__(672) void k_final(
    const float* __restrict__ mb,
    const float* __restrict__ rw1, const float* __restrict__ rb1,
    const float* __restrict__ rw2, const float* __restrict__ rb2,
    float* __restrict__ out) {
    int v = blockIdx.x;
    int tid = threadIdx.x;                 // 672 threads; 648 compute (8 b x 81 t-pairs)
    __shared__ float2 sg[768];             // G dup pairs: [j][s*16+c]
    __shared__ float2 sr1[256];            // rw1 dup pairs
    __shared__ float  s_mb[16], s_rb1[16], s_rw2[384], s_rb2[24];
    __shared__ float  part[648][17];
    __shared__ float  rm[8][16];

    for (int idx = tid; idx < 768; idx += 672) { float w = g_G[idx]; sg[idx]  = make_float2(w, w); }
    for (int idx = tid; idx < 256; idx += 672) { float w = rw1[idx]; sr1[idx] = make_float2(w, w); }
    for (int idx = tid; idx < 384; idx += 672) s_rw2[idx] = rw2[idx];
    if (tid < 16) { s_mb[tid] = mb[tid]; s_rb1[tid] = rb1[tid]; }
    if (tid < 24) s_rb2[tid] = rb2[tid];
    __syncthreads();

    if (tid < 648) {
        int b = tid / 81;
        int i = tid - b * 81;
        int t0 = 2 * i;                    // 81*2 = 162 exactly
        size_t off = (size_t)v * FDIM + ((size_t)b * TLEN + t0) * CH;

        float2 z[16];
#pragma unroll
        for (int j = 0; j < 16; j++) { float m = s_mb[j]; z[j] = make_float2(m, m); }

#pragma unroll
        for (int s = 0; s < 3; s++) {
            const __half* bp = (s == 0 ? g_H0 : (s == 1 ? g_P1 : g_P2)) + off;
            const uint4* rA = (const uint4*)bp;          // row t0   (16 halves)
            const uint4* rB = (const uint4*)(bp + CH);   // row t0+1
#pragma unroll
            for (int chunk = 0; chunk < 2; chunk++) {
                uint4 ua = rA[chunk], ub = rB[chunk];
                const half2* ha = (const half2*)&ua;
                const half2* hb = (const half2*)&ub;
                float2 h[8];
#pragma unroll
                for (int q = 0; q < 4; q++) {
                    float2 fa = __half22float2(ha[q]);   // (c=2q, c=2q+1) at t0
                    float2 fb = __half22float2(hb[q]);   // at t0+1
                    h[2*q]   = make_float2(fa.x, fb.x);
                    h[2*q+1] = make_float2(fa.y, fb.y);
                }
                int cb = chunk * 8;
#pragma unroll
                for (int c = 0; c < 8; c++) {
#pragma unroll
                    for (int j = 0; j < 16; j++)
                        z[j] = ffma2(sg[j * 48 + s * 16 + cb + c], h[c], z[j]);
                }
            }
        }

        float2 zr[16];
#pragma unroll
        for (int j = 0; j < 16; j++)
            zr[j] = make_float2(fmaxf(z[j].x, 0.f), fmaxf(z[j].y, 0.f));

#pragma unroll
        for (int i2 = 0; i2 < 16; i2++) {
            float rb = s_rb1[i2];
            float2 acc = make_float2(rb, rb);
#pragma unroll
            for (int j = 0; j < 16; j++)
                acc = ffma2(sr1[i2 * 16 + j], zr[j], acc);
            part[tid][i2] = fmaxf(acc.x, 0.f) + fmaxf(acc.y, 0.f);
        }
    }
    __syncthreads();

    if (tid < 128) {
        int b = tid >> 4, c = tid & 15;
        float s = 0.f;
#pragma unroll 9
        for (int k = 0; k < 81; k++) s += part[b * 81 + k][c];
        rm[b][c] = s * (1.f / (float)TLEN);
    }
    __syncthreads();

    if (tid < 192) {
        int b = tid / 24, o = tid - b * 24;
        float a = s_rb2[o];
#pragma unroll
        for (int c = 0; c < 16; c++) a += s_rw2[o * 16 + c] * rm[b][c];
        out[((size_t)b * 24 + o) * NNODE + v] = a;
    }
}

// ======================= launcher =======================
extern "C" void kernel_launch(void* const* d_in, const int* in_sizes, int n_in,
                              void* d_out, int out_size) {
    const float* x   = (const float*)d_in[0];
    const float* pw  = (const float*)d_in[1];
    const float* pb  = (const float*)d_in[2];
    const float* tw2 = (const float*)d_in[3];
    const float* tb2 = (const float*)d_in[4];
    const float* tw3 = (const float*)d_in[5];
    const float* tb3 = (const float*)d_in[6];
    const float* tw6 = (const float*)d_in[7];
    const float* tb6 = (const float*)d_in[8];
    const float* tw7 = (const float*)d_in[9];
    const float* tb7 = (const float*)d_in[10];
    const float* e1  = (const float*)d_in[11];
    const float* e2  = (const float*)d_in[12];
    const float* gw1 = (const float*)d_in[13];
    const float* gb1 = (const float*)d_in[14];
    const float* gw2 = (const float*)d_in[15];
    const float* gb2 = (const float*)d_in[16];
    const float* mw  = (const float*)d_in[17];
    const float* mb  = (const float*)d_in[18];
    const float* rw1 = (const float*)d_in[19];
    const float* rb1 = (const float*)d_in[20];
    const float* rw2 = (const float*)d_in[21];
    const float* rb2 = (const float*)d_in[22];

    __half* H0 = nullptr; __half* P1 = nullptr; __half* P2 = nullptr;
    cudaGetSymbolAddress((void**)&H0, g_H0);
    cudaGetSymbolAddress((void**)&P1, g_P1);
    cudaGetSymbolAddress((void**)&P2, g_P2);

    k_prep<<<(NNODE + 127) / 128, 128>>>(pw, pb, tw2, tb2, tw3, tb3, tw6, tb6, tw7, tb7,
                                         e1, gw1, gb1, e2, gw2, gb2, mw);
    k_topk<<<NNODE, 256>>>();
    k_tconv<<<NNODE, 192>>>(x);

    dim3 gs(NNODE, FDIM8 / 96);    // 1500 x 27
    k_spmm<<<gs, 96>>>(H0, P1);    // 4th launch -> profiled
    k_spmm<<<gs, 96>>>(P1, P2);

    k_final<<<NNODE, 672>>>(mb, rw1, rb1, rw2, rb2, (float*)d_out);
}

// round 17
// speedup vs baseline: 2.5435x; 1.0841x over previous
#include <cuda_runtime.h>
#include <cuda_fp16.h>
#include <cstdint>
#include <cstddef>
#include <climits>

#define NNODE 1500
#define T_IN  168
#define TLEN  162
#define BATCH 8
#define CH    16
#define EMBD  16
#define KTOP  12
#define NBRS  13            // KTOP + self
#define FDIM  (BATCH*CH*TLEN)   // 20736
#define FDIM8 (FDIM/8)          // 2592 = 27*96
#define ALPHA 1.5f
#define BETA  0.2f

// H-state layout: idx(v,b,t,c) = v*FDIM + (b*TLEN + t)*CH + c   (c innermost)
__device__ __half g_H0[(size_t)NNODE * FDIM];
__device__ __half g_P1[(size_t)NNODE * FDIM];
__device__ __half g_P2[(size_t)NNODE * FDIM];
__device__ float g_m1[NNODE * EMBD];
__device__ float g_m2[NNODE * EMBD];
__device__ float g_weff[CH * 8];
__device__ float g_beff[CH];
__device__ int   g_nbr[NNODE * NBRS];
__device__ float g_nw [NNODE * NBRS];
__device__ float g_G[768];          // folded 48->16 weights [j][s*16+c]

// ---------------- packed fp32x2 FMA (sm_103a FFMA2) ----------------
__device__ __forceinline__ float2 ffma2(float2 a, float2 b, float2 c) {
    unsigned long long au = *reinterpret_cast<unsigned long long*>(&a);
    unsigned long long bu = *reinterpret_cast<unsigned long long*>(&b);
    unsigned long long cu = *reinterpret_cast<unsigned long long*>(&c);
    unsigned long long du;
    asm("fma.rn.f32x2 %0, %1, %2, %3;" : "=l"(du) : "l"(au), "l"(bu), "l"(cu));
    return *reinterpret_cast<float2*>(&du);
}

// ============ K0: combined prep (weff fold + embeddings + G fold) ============
__global__ void k_prep(const float* pw, const float* pb,
                       const float* tw2, const float* tb2,
                       const float* tw3, const float* tb3,
                       const float* tw6, const float* tb6,
                       const float* tw7, const float* tb7,
                       const float* e1, const float* gw1, const float* gb1,
                       const float* e2, const float* gw2, const float* gb2,
                       const float* mw) {
    int n = blockIdx.x * 128 + threadIdx.x;
    if (n < NNODE) {
        float ev1[EMBD], ev2[EMBD];
#pragma unroll
        for (int i = 0; i < EMBD; i++) { ev1[i] = e1[n * EMBD + i]; ev2[i] = e2[n * EMBD + i]; }
#pragma unroll
        for (int e = 0; e < EMBD; e++) {
            float a1 = gb1[e], a2 = gb2[e];
#pragma unroll
            for (int k = 0; k < EMBD; k++) {
                a1 += ev1[k] * gw1[k * EMBD + e];
                a2 += ev2[k] * gw2[k * EMBD + e];
            }
            g_m1[n * EMBD + e] = tanhf(ALPHA * a1);
            g_m2[n * EMBD + e] = tanhf(ALPHA * a2);
        }
    }
    if (blockIdx.x == 0) {
        if (threadIdx.x < CH) {
            int c = threadIdx.x;
            int br = c >> 2, o = c & 3;
            const float* tw; const float* tb; int k;
            if      (br == 0) { tw = tw2; tb = tb2; k = 2; }
            else if (br == 1) { tw = tw3; tb = tb3; k = 3; }
            else if (br == 2) { tw = tw6; tb = tb6; k = 6; }
            else              { tw = tw7; tb = tb7; k = 7; }
            float bacc = tb[o];
            for (int j = 0; j < k; j++) {
                float wacc = 0.f;
                for (int ci = 0; ci < CH; ci++) {
                    float w = tw[(o * CH + ci) * k + j];
                    wacc += w * pw[ci];
                    bacc += w * pb[ci];
                }
                g_weff[c * 8 + j] = wacc;
            }
            g_beff[c] = bacc;
        }
        for (int idx = threadIdx.x; idx < 768; idx += 128) {
            int j = idx / 48, c = idx % 48;
            int hop = c >> 4, ci = c & 15;
            const float* row = mw + j * 48;
            float m1v = row[16 + ci], m2v = row[32 + ci];
            float g;
            if      (hop == 0) g = row[ci] + BETA * m1v + BETA * m2v;
            else if (hop == 1) g = (1.f - BETA) * m1v + BETA * (1.f - BETA) * m2v;
            else               g = (1.f - BETA) * (1.f - BETA) * m2v;
            g_G[idx] = g;
        }
    }
}

// ============ K1: warp-level tournament top-12 (no barriers in hot loop) ============
#define SEG 188
#define SLOTS 6

__global__ void k_topk() {
    int v = blockIdx.x;
    int tid = threadIdx.x;
    int w = tid >> 5, lane = tid & 31;

    float m1v[EMBD], m2v[EMBD];
#pragma unroll
    for (int e = 0; e < EMBD; e++) { m1v[e] = g_m1[v * EMBD + e]; m2v[e] = g_m2[v * EMBD + e]; }

    int base = w * SEG;
    int segEnd = min(base + SEG, NNODE);
    float vals[SLOTS];
    int   idxs[SLOTS];
#pragma unroll
    for (int k = 0; k < SLOTS; k++) {
        int idx = base + k * 32 + lane;
        if (idx < segEnd) {
            const float4* p2 = (const float4*)(g_m2 + idx * EMBD);
            const float4* p1 = (const float4*)(g_m1 + idx * EMBD);
            float d = 0.f;
#pragma unroll
            for (int q = 0; q < 4; q++) {
                float4 a2 = p2[q], a1 = p1[q];
                d += m1v[4*q+0]*a2.x - m2v[4*q+0]*a1.x;
                d += m1v[4*q+1]*a2.y - m2v[4*q+1]*a1.y;
                d += m1v[4*q+2]*a2.z - m2v[4*q+2]*a1.z;
                d += m1v[4*q+3]*a2.w - m2v[4*q+3]*a1.w;
            }
            float a = tanhf(ALPHA * d);
            vals[k] = a > 0.f ? a : 0.f;
            idxs[k] = idx;
        } else {
            vals[k] = -1.f;
            idxs[k] = INT_MAX;
        }
    }

    __shared__ float swv[8][KTOP];
    __shared__ int   swi[8][KTOP];

#pragma unroll
    for (int it = 0; it < KTOP; it++) {
        float bv = -1.f; int bi = INT_MAX;
#pragma unroll
        for (int k = 0; k < SLOTS; k++)
            if (vals[k] > bv || (vals[k] == bv && idxs[k] < bi)) { bv = vals[k]; bi = idxs[k]; }
#pragma unroll
        for (int off = 16; off; off >>= 1) {
            float ov = __shfl_xor_sync(0xffffffffu, bv, off);
            int   oi = __shfl_xor_sync(0xffffffffu, bi, off);
            if (ov > bv || (ov == bv && oi < bi)) { bv = ov; bi = oi; }
        }
#pragma unroll
        for (int k = 0; k < SLOTS; k++)
            if (idxs[k] == bi) vals[k] = -1.f;
        if (lane == 0) { swv[w][it] = bv; swi[w][it] = bi; }
    }
    __syncthreads();

    if (w == 0) {
        float mv[3]; int mi[3];
#pragma unroll
        for (int k = 0; k < 3; k++) {
            int j = lane + 32 * k;
            if (j < 96) { mv[k] = swv[j / KTOP][j % KTOP]; mi[k] = swi[j / KTOP][j % KTOP]; }
            else        { mv[k] = -1.f; mi[k] = INT_MAX; }
        }
        float myv = -1.f; int myi = 0;
        float sum = 0.f;
#pragma unroll
        for (int it = 0; it < KTOP; it++) {
            float bv = -1.f; int bi = INT_MAX;
#pragma unroll
            for (int k = 0; k < 3; k++)
                if (mv[k] > bv || (mv[k] == bv && mi[k] < bi)) { bv = mv[k]; bi = mi[k]; }
#pragma unroll
            for (int off = 16; off; off >>= 1) {
                float ov = __shfl_xor_sync(0xffffffffu, bv, off);
                int   oi = __shfl_xor_sync(0xffffffffu, bi, off);
                if (ov > bv || (ov == bv && oi < bi)) { bv = ov; bi = oi; }
            }
#pragma unroll
            for (int k = 0; k < 3; k++)
                if (mi[k] == bi) mv[k] = -1.f;
            if (lane == it) { myv = bv; myi = bi; }
            sum += bv;
        }
        float inv = 1.f / (1.f + sum);
        if (lane < KTOP) {
            g_nbr[v * NBRS + lane] = myi;
            g_nw [v * NBRS + lane] = myv * inv;
        }
        if (lane == 0) {
            g_nbr[v * NBRS + KTOP] = v;
            g_nw [v * NBRS + KTOP] = inv;
        }
    }
}

// ============ K2: folded inception temporal conv -> H0[v][b][t][c] (fp16, coalesced) ============
__device__ __forceinline__ constexpr int KC(int c) {
    return c < 4 ? 2 : (c < 8 ? 3 : (c < 12 ? 6 : 7));
}

__global__ void k_tconv(const float* __restrict__ x) {
    int n = blockIdx.x;
    int tid = threadIdx.x;                    // 192 threads
    __shared__ float xs[BATCH][T_IN];
    __shared__ float swv[128];
    __shared__ float sbv[16];
    for (int i = tid; i < BATCH * T_IN; i += 192) {
        int b = i / T_IN, t = i - b * T_IN;
        xs[b][t] = x[(size_t)(b * T_IN + t) * NNODE + n];
    }
    if (tid < 128) swv[tid] = g_weff[tid];
    if (tid < 16)  sbv[tid] = g_beff[tid];
    __syncthreads();
    if (tid >= TLEN) return;

    float wr[16][8];
#pragma unroll
    for (int c = 0; c < 16; c++) {
        const int k = KC(c);
#pragma unroll
        for (int j = 0; j < 8; j++)
            if (j < k) wr[c][j] = swv[c * 8 + j];
    }
    float bb[16];
#pragma unroll
    for (int c = 0; c < 16; c++) bb[c] = sbv[c];

    __half* outp = g_H0 + (size_t)n * FDIM;
#pragma unroll
    for (int b = 0; b < BATCH; b++) {
        half2 pk[8];
#pragma unroll
        for (int q = 0; q < 8; q++) {
            float accs[2];
#pragma unroll
            for (int h = 0; h < 2; h++) {
                int c = 2 * q + h;
                const int k = KC(c);
                float acc = bb[c];
#pragma unroll
                for (int j = 0; j < k; j++)
                    acc = fmaf(wr[c][j], xs[b][tid + 7 - k + j], acc);
                accs[h] = fmaxf(acc, 0.f);
            }
            pk[q] = __floats2half2_rn(accs[0], accs[1]);
        }
        uint4* dst = (uint4*)(outp + ((size_t)b * TLEN + tid) * CH);
        dst[0] = ((uint4*)pk)[0];
        dst[1] = ((uint4*)pk)[1];
    }
}

// ============ K3/K4: pure propagation P = Â·src, uint4 (8-half) L2 gathers ============
__global__ void k_spmm(const __half* __restrict__ src, __half* __restrict__ dst) {
    int v = blockIdx.x;
    int f8 = blockIdx.y * 96 + threadIdx.x;   // FDIM8=2592 = 27*96
    __shared__ int   nb[NBRS];
    __shared__ float nw[NBRS];
    if (threadIdx.x < NBRS) {
        nb[threadIdx.x] = g_nbr[v * NBRS + threadIdx.x];
        nw[threadIdx.x] = g_nw [v * NBRS + threadIdx.x];
    }
    __syncthreads();
    const uint4* s8 = (const uint4*)src;
    float2 a0 = make_float2(0.f, 0.f), a1 = a0, a2 = a0, a3 = a0;
#pragma unroll
    for (int j = 0; j < NBRS; j++) {
        uint4 hv = s8[(size_t)nb[j] * FDIM8 + f8];
        float wj = nw[j];
        float2 w2 = make_float2(wj, wj);
        const half2* h = (const half2*)&hv;
        a0 = ffma2(w2, __half22float2(h[0]), a0);
        a1 = ffma2(w2, __half22float2(h[1]), a1);
        a2 = ffma2(w2, __half22float2(h[2]), a2);
        a3 = ffma2(w2, __half22float2(h[3]), a3);
    }
    uint4 r;
    ((half2*)&r)[0] = __float22half2_rn(a0);
    ((half2*)&r)[1] = __float22half2_rn(a1);
    ((half2*)&r)[2] = __float22half2_rn(a2);
    ((half2*)&r)[3] = __float22half2_rn(a3);
    ((uint4*)dst)[(size_t)v * FDIM8 + f8] = r;
}

// ============ K5: MLP head; thread = (t-pair, 2 batches) — weight LDS amortized 2x ============
__global__ __launch_bounds__(336) void k_final(
    const float* __restrict__ mb,
    const float* __restrict__ rw1, const float* __restrict__ rb1,
    const float* __restrict__ rw2, const float* __restrict__ rb2,
    float* __restrict__ out) {
    int v = blockIdx.x;
    int tid = threadIdx.x;                 // 336 threads; 324 compute (4 bb x 81 t-pairs)
    __shared__ float2 sg[768];             // G dup pairs: [j][s*16+c]
    __shared__ float2 sr1[256];            // rw1 dup pairs
    __shared__ float  s_mb[16], s_rb1[16], s_rw2[384], s_rb2[24];
    __shared__ float  part[648][17];       // row = b*81 + t-pair
    __shared__ float  rm[8][16];

    for (int idx = tid; idx < 768; idx += 336) { float w = g_G[idx]; sg[idx]  = make_float2(w, w); }
    for (int idx = tid; idx < 256; idx += 336) { float w = rw1[idx]; sr1[idx] = make_float2(w, w); }
    for (int idx = tid; idx < 384; idx += 336) s_rw2[idx] = rw2[idx];
    if (tid < 16) { s_mb[tid] = mb[tid]; s_rb1[tid] = rb1[tid]; }
    if (tid < 24) s_rb2[tid] = rb2[tid];
    __syncthreads();

    if (tid < 324) {
        int bb = tid / 81;                 // 0..3  -> handles batches bb and bb+4
        int i  = tid - bb * 81;
        int t0 = 2 * i;
        size_t off0 = (size_t)v * FDIM + ((size_t)bb * TLEN + t0) * CH;
        size_t off1 = off0 + (size_t)4 * TLEN * CH;

        float2 z0[16], z1[16];
#pragma unroll
        for (int j = 0; j < 16; j++) {
            float m = s_mb[j];
            z0[j] = make_float2(m, m);
            z1[j] = z0[j];
        }

#pragma unroll
        for (int s = 0; s < 3; s++) {
            const __half* base = (s == 0 ? g_H0 : (s == 1 ? g_P1 : g_P2));
            const uint4* rA0 = (const uint4*)(base + off0);        // batch bb,   t0
            const uint4* rB0 = (const uint4*)(base + off0 + CH);   // batch bb,   t0+1
            const uint4* rA1 = (const uint4*)(base + off1);        // batch bb+4, t0
            const uint4* rB1 = (const uint4*)(base + off1 + CH);   // batch bb+4, t0+1
#pragma unroll
            for (int chunk = 0; chunk < 2; chunk++) {
                uint4 ua0 = rA0[chunk], ub0 = rB0[chunk];
                uint4 ua1 = rA1[chunk], ub1 = rB1[chunk];
                const half2* ha0 = (const half2*)&ua0;
                const half2* hb0 = (const half2*)&ub0;
                const half2* ha1 = (const half2*)&ua1;
                const half2* hb1 = (const half2*)&ub1;
                float2 h0[8], h1[8];
#pragma unroll
                for (int q = 0; q < 4; q++) {
                    float2 fa0 = __half22float2(ha0[q]);
                    float2 fb0 = __half22float2(hb0[q]);
                    float2 fa1 = __half22float2(ha1[q]);
                    float2 fb1 = __half22float2(hb1[q]);
                    h0[2*q]   = make_float2(fa0.x, fb0.x);
                    h0[2*q+1] = make_float2(fa0.y, fb0.y);
                    h1[2*q]   = make_float2(fa1.x, fb1.x);
                    h1[2*q+1] = make_float2(fa1.y, fb1.y);
                }
                int cb = chunk * 8;
#pragma unroll
                for (int c = 0; c < 8; c++) {
#pragma unroll
                    for (int j = 0; j < 16; j++) {
                        float2 w = sg[j * 48 + s * 16 + cb + c];
                        z0[j] = ffma2(w, h0[c], z0[j]);
                        z1[j] = ffma2(w, h1[c], z1[j]);
                    }
                }
            }
        }

#pragma unroll
        for (int j = 0; j < 16; j++) {
            z0[j] = make_float2(fmaxf(z0[j].x, 0.f), fmaxf(z0[j].y, 0.f));
            z1[j] = make_float2(fmaxf(z1[j].x, 0.f), fmaxf(z1[j].y, 0.f));
        }

#pragma unroll
        for (int i2 = 0; i2 < 16; i2++) {
            float rb = s_rb1[i2];
            float2 a0 = make_float2(rb, rb), a1 = a0;
#pragma unroll
            for (int j = 0; j < 16; j++) {
                float2 w = sr1[i2 * 16 + j];
                a0 = ffma2(w, z0[j], a0);
                a1 = ffma2(w, z1[j], a1);
            }
            part[tid][i2]       = fmaxf(a0.x, 0.f) + fmaxf(a0.y, 0.f);
            part[tid + 324][i2] = fmaxf(a1.x, 0.f) + fmaxf(a1.y, 0.f);
        }
    }
    __syncthreads();

    if (tid < 128) {
        int b = tid >> 4, c = tid & 15;
        float s = 0.f;
#pragma unroll 9
        for (int k = 0; k < 81; k++) s += part[b * 81 + k][c];
        rm[b][c] = s * (1.f / (float)TLEN);
    }
    __syncthreads();

    if (tid < 192) {
        int b = tid / 24, o = tid - b * 24;
        float a = s_rb2[o];
#pragma unroll
        for (int c = 0; c < 16; c++) a += s_rw2[o * 16 + c] * rm[b][c];
        out[((size_t)b * 24 + o) * NNODE + v] = a;
    }
}

// ======================= launcher =======================
extern "C" void kernel_launch(void* const* d_in, const int* in_sizes, int n_in,
                              void* d_out, int out_size) {
    const float* x   = (const float*)d_in[0];
    const float* pw  = (const float*)d_in[1];
    const float* pb  = (const float*)d_in[2];
    const float* tw2 = (const float*)d_in[3];
    const float* tb2 = (const float*)d_in[4];
    const float* tw3 = (const float*)d_in[5];
    const float* tb3 = (const float*)d_in[6];
    const float* tw6 = (const float*)d_in[7];
    const float* tb6 = (const float*)d_in[8];
    const float* tw7 = (const float*)d_in[9];
    const float* tb7 = (const float*)d_in[10];
    const float* e1  = (const float*)d_in[11];
    const float* e2  = (const float*)d_in[12];
    const float* gw1 = (const float*)d_in[13];
    const float* gb1 = (const float*)d_in[14];
    const float* gw2 = (const float*)d_in[15];
    const float* gb2 = (const float*)d_in[16];
    const float* mw  = (const float*)d_in[17];
    const float* mb  = (const float*)d_in[18];
    const float* rw1 = (const float*)d_in[19];
    const float* rb1 = (const float*)d_in[20];
    const float* rw2 = (const float*)d_in[21];
    const float* rb2 = (const float*)d_in[22];

    __half* H0 = nullptr; __half* P1 = nullptr; __half* P2 = nullptr;
    cudaGetSymbolAddress((void**)&H0, g_H0);
    cudaGetSymbolAddress((void**)&P1, g_P1);
    cudaGetSymbolAddress((void**)&P2, g_P2);

    k_prep<<<(NNODE + 127) / 128, 128>>>(pw, pb, tw2, tb2, tw3, tb3, tw6, tb6, tw7, tb7,
                                         e1, gw1, gb1, e2, gw2, gb2, mw);
    k_topk<<<NNODE, 256>>>();
    k_tconv<<<NNODE, 192>>>(x);

    dim3 gs(NNODE, FDIM8 / 96);    // 1500 x 27
    k_spmm<<<gs, 96>>>(H0, P1);    // 4th launch -> profiled
    k_spmm<<<gs, 96>>>(P1, P2);

    k_final<<<NNODE, 336>>>(mb, rw1, rb1, rw2, rb2, (float*)d_out);
}